// round 2
// baseline (speedup 1.0000x reference)
#include <cuda_runtime.h>
#include <math.h>

// Problem dims
#define NB 64
#define NS 256
#define NH 1024
#define NE 512
#define NV 10000
#define NT 64
#define ND 512
#define NG 2048     // 4*D
#define NCK 2048    // E+H+D (lstm concat input)
#define NXK 1536    // E+H

// Output layout: decoder_outputs, h, c, attentions (row-major, concatenated)
#define OUT_LOG 0
#define OUT_H   (NB*NT*NV)
#define OUT_C   (OUT_H + 2*NB*ND)
#define OUT_ATTN (OUT_C + 2*NB*ND)

// Scratch (device globals: no allocation allowed)
__device__ float g_Uk[NB*NS*NH];     // 64 MB: enc @ Ua^T, precomputed once
__device__ float g_qWa[NB*NH];
__device__ float g_scores[NB*NS];
__device__ float g_w[NB*NS];
__device__ float g_ctx[NB*NH];
__device__ float g_xcat[2*NB*NCK];   // [emb | ctx | h_dir] per direction
__device__ float g_h[2*NB*ND];
__device__ float g_c[2*NB*ND];
__device__ float g_gates[2*NB*NG];

__device__ __forceinline__ float tanh_fast(float x) {
    float y;
    asm("tanh.approx.f32 %0, %1;" : "=f"(y) : "f"(x));
    return y;
}
__device__ __forceinline__ float sigmoid_acc(float x) {
    return 1.0f / (1.0f + __expf(-x));
}

// ---------------------------------------------------------------------------
// init: copy initial states
__global__ __launch_bounds__(256) void k_init(const float* __restrict__ h0,
                                              const float* __restrict__ c0) {
    int idx = blockIdx.x * 256 + threadIdx.x;   // 65536
    g_h[idx] = h0[idx];
    g_c[idx] = c0[idx];
}

// ---------------------------------------------------------------------------
// Uk[bs][n] = sum_k enc[bs][k] * Ua[n][k]   (M=16384, N=1024, K=1024)
// classic 128x128x8 SGEMM, 256 threads, 8x8 per thread
__global__ __launch_bounds__(256) void k_uk(const float* __restrict__ A,
                                            const float* __restrict__ W) {
    const int K = NH, N = NH;
    int n0 = blockIdx.x * 128, m0 = blockIdx.y * 128;
    __shared__ float As[8][128];
    __shared__ float Bs[8][128];
    int tid = threadIdx.x;
    int lr = tid >> 1;            // load row 0..127
    int lc = (tid & 1) * 4;       // load col base {0,4}
    int tx = tid & 15, ty = tid >> 4;
    float acc[8][8];
#pragma unroll
    for (int i = 0; i < 8; i++)
#pragma unroll
        for (int j = 0; j < 8; j++) acc[i][j] = 0.f;

    const float* Aptr = A + (m0 + lr) * K + lc;
    const float* Wptr = W + (n0 + lr) * K + lc;

    for (int k0 = 0; k0 < K; k0 += 8) {
        float4 av = *(const float4*)(Aptr + k0);
        float4 bv = *(const float4*)(Wptr + k0);
        As[lc + 0][lr] = av.x; As[lc + 1][lr] = av.y;
        As[lc + 2][lr] = av.z; As[lc + 3][lr] = av.w;
        Bs[lc + 0][lr] = bv.x; Bs[lc + 1][lr] = bv.y;
        Bs[lc + 2][lr] = bv.z; Bs[lc + 3][lr] = bv.w;
        __syncthreads();
#pragma unroll
        for (int kk = 0; kk < 8; kk++) {
            float4 a0 = *(const float4*)&As[kk][ty * 4];
            float4 a1 = *(const float4*)&As[kk][64 + ty * 4];
            float4 b0 = *(const float4*)&Bs[kk][tx * 4];
            float4 b1 = *(const float4*)&Bs[kk][64 + tx * 4];
            float a[8] = {a0.x, a0.y, a0.z, a0.w, a1.x, a1.y, a1.z, a1.w};
            float b[8] = {b0.x, b0.y, b0.z, b0.w, b1.x, b1.y, b1.z, b1.w};
#pragma unroll
            for (int i = 0; i < 8; i++)
#pragma unroll
                for (int j = 0; j < 8; j++) acc[i][j] += a[i] * b[j];
        }
        __syncthreads();
    }
#pragma unroll
    for (int hi = 0; hi < 2; hi++)
#pragma unroll
        for (int i = 0; i < 4; i++) {
            int m = m0 + hi * 64 + ty * 4 + i;
            float* cp = g_Uk + m * N + n0;
            int r = hi * 4 + i;
            *(float4*)(cp + tx * 4) =
                make_float4(acc[r][0], acc[r][1], acc[r][2], acc[r][3]);
            *(float4*)(cp + 64 + tx * 4) =
                make_float4(acc[r][4], acc[r][5], acc[r][6], acc[r][7]);
        }
}

// ---------------------------------------------------------------------------
// per-step init: zero qWa, seed gates with biases
__global__ __launch_bounds__(256) void k_step_init(const float* __restrict__ bihf,
                                                   const float* __restrict__ bhhf,
                                                   const float* __restrict__ bihb,
                                                   const float* __restrict__ bhhb) {
    int idx = blockIdx.x * 256 + threadIdx.x;   // grid 1280 -> 327680
    if (idx < NB * NH) {
        g_qWa[idx] = 0.f;
    } else {
        int r = idx - NB * NH;                  // 0 .. 262143
        int d = r >> 17;                        // /(NB*NG=131072)
        int j = r & (NG - 1);
        g_gates[r] = d ? (bihb[j] + bhhb[j]) : (bihf[j] + bhhf[j]);
    }
}

// ---------------------------------------------------------------------------
// shared 64x32x16 tile helpers (128 threads, 4x4 per thread)
__device__ __forceinline__ void load_query_tile(float As[16][64], int tid, int k0) {
    // A[m][k] = h[k/512][m][k%512]  (query / out-vector layout)
    int m = tid >> 1;
    int c = (tid & 1) * 8;
    int kq = k0 + c;
    int dir = kq >> 9;
    const float* ap = g_h + dir * (NB * ND) + m * ND + (kq & 511);
    float4 v0 = *(const float4*)ap;
    float4 v1 = *(const float4*)(ap + 4);
    As[c + 0][m] = v0.x; As[c + 1][m] = v0.y; As[c + 2][m] = v0.z; As[c + 3][m] = v0.w;
    As[c + 4][m] = v1.x; As[c + 5][m] = v1.y; As[c + 6][m] = v1.z; As[c + 7][m] = v1.w;
}

__device__ __forceinline__ void mm_tile(const float (&As)[16][64],
                                        const float (&Bs)[16][32],
                                        float (&acc)[4][4], int tx, int ty) {
#pragma unroll
    for (int kk = 0; kk < 16; kk++) {
        float4 av = *(const float4*)&As[kk][ty * 4];
        float4 bv = *(const float4*)&Bs[kk][tx * 4];
        float a[4] = {av.x, av.y, av.z, av.w};
        float b[4] = {bv.x, bv.y, bv.z, bv.w};
#pragma unroll
        for (int i = 0; i < 4; i++)
#pragma unroll
            for (int j = 0; j < 4; j++) acc[i][j] += a[i] * b[j];
    }
}

// ---------------------------------------------------------------------------
// qWa[64,1024] = query @ Wa^T   split-K=8, atomic accumulate
__global__ __launch_bounds__(128) void k_qwa(const float* __restrict__ Wa) {
    int n0 = blockIdx.x * 32;
    int kbase = blockIdx.y * 128;
    __shared__ float As[16][64];
    __shared__ float Bs[16][32];
    int tid = threadIdx.x;
    int tx = tid & 7, ty = tid >> 3;
    float acc[4][4] = {};
    for (int k0 = kbase; k0 < kbase + 128; k0 += 16) {
        load_query_tile(As, tid, k0);
        {
            int n = n0 + (tid >> 2);
            int c = (tid & 3) * 4;
            float4 v = *(const float4*)(Wa + n * NH + k0 + c);
            Bs[c + 0][tid >> 2] = v.x; Bs[c + 1][tid >> 2] = v.y;
            Bs[c + 2][tid >> 2] = v.z; Bs[c + 3][tid >> 2] = v.w;
        }
        __syncthreads();
        mm_tile(As, Bs, acc, tx, ty);
        __syncthreads();
    }
#pragma unroll
    for (int i = 0; i < 4; i++) {
        int m = ty * 4 + i;
#pragma unroll
        for (int j = 0; j < 4; j++)
            atomicAdd(&g_qWa[m * NH + n0 + tx * 4 + j], acc[i][j]);
    }
}

// ---------------------------------------------------------------------------
// scores[b][s] = sum_h Va[h] * tanh(qWa[b][h] + Uk[b][s][h])  (warp per (b,s))
__global__ __launch_bounds__(256) void k_scores(const float* __restrict__ Va) {
    int w = threadIdx.x >> 5, l = threadIdx.x & 31;
    int bs = blockIdx.x * 8 + w;
    int b = bs >> 8;
    const float4* uk = (const float4*)(g_Uk) + bs * (NH / 4);
    const float4* q = (const float4*)(g_qWa) + b * (NH / 4);
    const float4* v = (const float4*)Va;
    float sum = 0.f;
#pragma unroll
    for (int i = 0; i < 8; i++) {
        int idx = l + 32 * i;
        float4 u = uk[idx], qq = q[idx], vv = v[idx];
        sum += vv.x * tanh_fast(u.x + qq.x);
        sum += vv.y * tanh_fast(u.y + qq.y);
        sum += vv.z * tanh_fast(u.z + qq.z);
        sum += vv.w * tanh_fast(u.w + qq.w);
    }
#pragma unroll
    for (int o = 16; o; o >>= 1) sum += __shfl_xor_sync(0xffffffffu, sum, o);
    if (!l) g_scores[bs] = sum;
}

// ---------------------------------------------------------------------------
// softmax over S per b; writes g_w and attentions output
__global__ __launch_bounds__(256) void k_softmax(const unsigned char* __restrict__ mask,
                                                 float* __restrict__ out, int t) {
    int b = blockIdx.x, s = threadIdx.x;
    int lane = s & 31, wid = s >> 5;
    float v = g_scores[b * NS + s];
    if (mask[b * NS + s]) v = -1e30f;
    float m = v;
#pragma unroll
    for (int o = 16; o; o >>= 1) m = fmaxf(m, __shfl_xor_sync(0xffffffffu, m, o));
    __shared__ float red[8];
    if (!lane) red[wid] = m;
    __syncthreads();
    float bm = red[0];
#pragma unroll
    for (int i = 1; i < 8; i++) bm = fmaxf(bm, red[i]);
    float e = __expf(v - bm);
    float sum = e;
#pragma unroll
    for (int o = 16; o; o >>= 1) sum += __shfl_xor_sync(0xffffffffu, sum, o);
    __syncthreads();
    if (!lane) red[wid] = sum;
    __syncthreads();
    float bs = 0.f;
#pragma unroll
    for (int i = 0; i < 8; i++) bs += red[i];
    float w = e / bs;
    g_w[b * NS + s] = w;
    out[b * NT * NS + t * NS + s] = w;
}

// ---------------------------------------------------------------------------
// ctx[b][:] = sum_s w[b][s] * enc[b][s][:]   (grid 256: b x quarter, 64 thr)
__global__ __launch_bounds__(64) void k_ctx(const float* __restrict__ enc) {
    int b = blockIdx.x >> 2, q = blockIdx.x & 3;
    __shared__ float ws[NS];
    for (int i = threadIdx.x; i < NS; i += 64) ws[i] = g_w[b * NS + i];
    __syncthreads();
    int c = q * 64 + threadIdx.x;                 // float4 column 0..255
    const float4* e4 = (const float4*)(enc) + (size_t)b * NS * 256 + c;
    float4 acc = make_float4(0.f, 0.f, 0.f, 0.f);
    for (int s = 0; s < NS; s++) {
        float4 ev = e4[(size_t)s * 256];
        float wv = ws[s];
        acc.x += wv * ev.x; acc.y += wv * ev.y;
        acc.z += wv * ev.z; acc.w += wv * ev.w;
    }
    ((float4*)g_ctx)[b * 256 + c] = acc;
}

// ---------------------------------------------------------------------------
// xcat[d][b][:] = [emb[tok[b]] | ctx[b] | h[d][b]]
__global__ __launch_bounds__(256) void k_xcat(const int* __restrict__ target,
                                              const int* __restrict__ sos,
                                              const float* __restrict__ emb, int t) {
    int idx = blockIdx.x * 256 + threadIdx.x;     // 262144
    int d = idx >> 17;
    int r = idx & 131071;
    int b = r >> 11;
    int j = r & 2047;
    float v;
    if (j < NE) {
        int tok = (t == 0) ? sos[0] : target[b * NT + t - 1];
        v = emb[tok * NE + j];
    } else if (j < NXK) {
        v = g_ctx[b * NH + (j - NE)];
    } else {
        v = g_h[d * NB * ND + b * ND + (j - NXK)];
    }
    g_xcat[idx] = v;
}

// ---------------------------------------------------------------------------
// gates[d][b][n] += xcat[d][b][:] @ [Wih_d | Whh_d]^T    split-K=4 (512 chunks)
__global__ __launch_bounds__(128) void k_lstm(const float* __restrict__ Wihf,
                                              const float* __restrict__ Whhf,
                                              const float* __restrict__ Wihb,
                                              const float* __restrict__ Whhb) {
    int n0 = blockIdx.x * 32;
    int kc = blockIdx.y;      // 0..3 (0-2: Wih, 3: Whh)
    int d = blockIdx.z;
    const float* Bw;
    int ldb, kofs;
    if (kc < 3) { Bw = d ? Wihb : Wihf; ldb = NXK; kofs = kc * 512; }
    else        { Bw = d ? Whhb : Whhf; ldb = ND;  kofs = 0; }
    const float* Aa = g_xcat + d * NB * NCK + kc * 512;

    __shared__ float As[16][64];
    __shared__ float Bs[16][32];
    int tid = threadIdx.x;
    int tx = tid & 7, ty = tid >> 3;
    float acc[4][4] = {};
    for (int kl = 0; kl < 512; kl += 16) {
        {
            int m = tid >> 1;
            int c = (tid & 1) * 8;
            const float* ap = Aa + m * NCK + kl + c;
            float4 v0 = *(const float4*)ap;
            float4 v1 = *(const float4*)(ap + 4);
            As[c + 0][m] = v0.x; As[c + 1][m] = v0.y; As[c + 2][m] = v0.z; As[c + 3][m] = v0.w;
            As[c + 4][m] = v1.x; As[c + 5][m] = v1.y; As[c + 6][m] = v1.z; As[c + 7][m] = v1.w;
        }
        {
            int n = n0 + (tid >> 2);
            int c = (tid & 3) * 4;
            float4 v = *(const float4*)(Bw + n * ldb + kofs + kl + c);
            Bs[c + 0][tid >> 2] = v.x; Bs[c + 1][tid >> 2] = v.y;
            Bs[c + 2][tid >> 2] = v.z; Bs[c + 3][tid >> 2] = v.w;
        }
        __syncthreads();
        mm_tile(As, Bs, acc, tx, ty);
        __syncthreads();
    }
#pragma unroll
    for (int i = 0; i < 4; i++) {
        int m = ty * 4 + i;
#pragma unroll
        for (int j = 0; j < 4; j++)
            atomicAdd(&g_gates[d * NB * NG + m * NG + n0 + tx * 4 + j], acc[i][j]);
    }
}

// ---------------------------------------------------------------------------
// LSTM pointwise (torch gate order i,f,g,o) — accurate transcendentals
__global__ __launch_bounds__(256) void k_cell() {
    int idx = blockIdx.x * 256 + threadIdx.x;    // 65536
    int d = idx >> 15;
    int r = idx & 32767;
    int b = r >> 9;
    int j = r & 511;
    const float* gr = g_gates + d * NB * NG + b * NG;
    float gi = gr[j], gf = gr[512 + j], gg = gr[1024 + j], go = gr[1536 + j];
    float c = g_c[idx];
    float c2 = sigmoid_acc(gf) * c + sigmoid_acc(gi) * tanhf(gg);
    g_c[idx] = c2;
    g_h[idx] = sigmoid_acc(go) * tanhf(c2);
}

// ---------------------------------------------------------------------------
// logits[b][v] = out_vec[b][:] @ out_W[v][:] + out_b[v]
__global__ __launch_bounds__(128) void k_logits(const float* __restrict__ outW,
                                                const float* __restrict__ outb,
                                                float* __restrict__ out, int t) {
    int n0 = blockIdx.x * 32;
    __shared__ float As[16][64];
    __shared__ float Bs[16][32];
    int tid = threadIdx.x;
    int tx = tid & 7, ty = tid >> 3;
    float acc[4][4] = {};
    for (int k0 = 0; k0 < NH; k0 += 16) {
        load_query_tile(As, tid, k0);
        {
            int n = n0 + (tid >> 2);
            int c = (tid & 3) * 4;
            float4 v = make_float4(0.f, 0.f, 0.f, 0.f);
            if (n < NV) v = *(const float4*)(outW + n * NH + k0 + c);
            Bs[c + 0][tid >> 2] = v.x; Bs[c + 1][tid >> 2] = v.y;
            Bs[c + 2][tid >> 2] = v.z; Bs[c + 3][tid >> 2] = v.w;
        }
        __syncthreads();
        mm_tile(As, Bs, acc, tx, ty);
        __syncthreads();
    }
#pragma unroll
    for (int i = 0; i < 4; i++) {
        int m = ty * 4 + i;
#pragma unroll
        for (int j = 0; j < 4; j++) {
            int n = n0 + tx * 4 + j;
            if (n < NV)
                out[OUT_LOG + m * NT * NV + t * NV + n] = acc[i][j] + outb[n];
        }
    }
}

// ---------------------------------------------------------------------------
__global__ __launch_bounds__(256) void k_final(float* __restrict__ out) {
    int idx = blockIdx.x * 256 + threadIdx.x;   // 65536
    out[OUT_H + idx] = g_h[idx];
    out[OUT_C + idx] = g_c[idx];
}

// ---------------------------------------------------------------------------
extern "C" void kernel_launch(void* const* d_in, const int* in_sizes, int n_in,
                              void* d_out, int out_size) {
    (void)in_sizes; (void)n_in; (void)out_size;
    const float* enc   = (const float*)d_in[0];
    const float* h0    = (const float*)d_in[1];
    const float* c0    = (const float*)d_in[2];
    const int* target  = (const int*)d_in[3];
    const unsigned char* mask = (const unsigned char*)d_in[4];
    const int* sos     = (const int*)d_in[5];
    const float* emb   = (const float*)d_in[6];
    const float* Wa    = (const float*)d_in[7];
    const float* Ua    = (const float*)d_in[8];
    const float* Va    = (const float*)d_in[9];
    const float* outW  = (const float*)d_in[10];
    const float* outb  = (const float*)d_in[11];
    const float* Wihf  = (const float*)d_in[12];
    const float* Whhf  = (const float*)d_in[13];
    const float* bihf  = (const float*)d_in[14];
    const float* bhhf  = (const float*)d_in[15];
    const float* Wihb  = (const float*)d_in[16];
    const float* Whhb  = (const float*)d_in[17];
    const float* bihb  = (const float*)d_in[18];
    const float* bhhb  = (const float*)d_in[19];
    float* out = (float*)d_out;

    k_init<<<256, 256>>>(h0, c0);
    k_uk<<<dim3(8, 128), 256>>>(enc, Ua);

    for (int t = 0; t < NT; t++) {
        k_step_init<<<1280, 256>>>(bihf, bhhf, bihb, bhhb);
        k_qwa<<<dim3(32, 8), 128>>>(Wa);
        k_scores<<<2048, 256>>>(Va);
        k_softmax<<<64, 256>>>(mask, out + OUT_ATTN, t);
        k_ctx<<<256, 64>>>(enc);
        k_xcat<<<1024, 256>>>(target, sos, emb, t);
        k_lstm<<<dim3(64, 4, 2), 128>>>(Wihf, Whhf, Wihb, Whhb);
        k_cell<<<256, 256>>>();
        k_logits<<<313, 128>>>(outW, outb, out, t);
    }
    k_final<<<256, 256>>>(out);
}

// round 3
// speedup vs baseline: 1.6516x; 1.6516x over previous
#include <cuda_runtime.h>
#include <math.h>
#include <stdint.h>

// Problem dims
#define NB 64
#define NS 256
#define NH 1024
#define NE 512
#define NV 10000
#define NT 64
#define ND 512
#define NG 2048     // 4*D
#define NCK 2048    // E+H+D (lstm concat input)
#define NXK 1536    // E+H

// Output layout: decoder_outputs, h, c, attentions (row-major, concatenated)
#define OUT_LOG 0
#define OUT_H   (NB*NT*NV)
#define OUT_C   (OUT_H + 2*NB*ND)
#define OUT_ATTN (OUT_C + 2*NB*ND)

// ---------------------------------------------------------------------------
// Scratch (device globals: no allocation allowed)
__device__ float g_Uk[NB*NS*NH];        // 64 MB
__device__ float g_qWa[NB*NH];
__device__ float g_scores[NB*NS];
__device__ float g_w[NB*NS];
__device__ float g_ctx[NB*NH];
__device__ float g_xcat[2*NB*NCK];      // [emb | ctx | h_dir], tf32-rounded
__device__ float g_hcat[NB*NH];         // [b][dir*512+j], exact fp32
__device__ float g_hcat32[NB*NH];       // tf32-rounded copy (GEMM activations)
__device__ float g_c[2*NB*ND];
__device__ float g_gates[2*NB*NG];
// tf32-rounded weight / input copies
__device__ float g_r_outW[NV*NH];       // 41 MB
__device__ float g_r_Wa[NH*NH];
__device__ float g_r_Ua[NH*NH];
__device__ float g_r_Wih[2][NG*NXK];
__device__ float g_r_Whh[2][NG*ND];
__device__ float g_enc32[NB*NS*NH];     // 64 MB

// ---------------------------------------------------------------------------
__device__ __forceinline__ float tanh_fast(float x) {
    float y;
    asm("tanh.approx.f32 %0, %1;" : "=f"(y) : "f"(x));
    return y;
}
__device__ __forceinline__ float sigmoid_acc(float x) {
    return 1.0f / (1.0f + __expf(-x));
}
__device__ __forceinline__ float rna_tf32(float x) {
    uint32_t u;
    asm("cvt.rna.tf32.f32 %0, %1;" : "=r"(u) : "f"(x));
    return __uint_as_float(u);
}
__device__ __forceinline__ void cp16(void* s, const void* g) {
    uint32_t sa = (uint32_t)__cvta_generic_to_shared(s);
    asm volatile("cp.async.cg.shared.global [%0], [%1], 16;\n" :: "r"(sa), "l"(g));
}
__device__ __forceinline__ void cp_commit() {
    asm volatile("cp.async.commit_group;\n");
}
__device__ __forceinline__ void cp_wait1() {
    asm volatile("cp.async.wait_group 1;\n");
}
__device__ __forceinline__ void cp_wait0() {
    asm volatile("cp.async.wait_group 0;\n");
}
__device__ __forceinline__ void mma_tf32(float (&d)[4], uint32_t a0, uint32_t a1,
                                         uint32_t a2, uint32_t a3,
                                         uint32_t b0, uint32_t b1) {
    asm volatile(
        "mma.sync.aligned.m16n8k8.row.col.f32.tf32.tf32.f32 "
        "{%0,%1,%2,%3}, {%4,%5,%6,%7}, {%8,%9}, {%0,%1,%2,%3};\n"
        : "+f"(d[0]), "+f"(d[1]), "+f"(d[2]), "+f"(d[3])
        : "r"(a0), "r"(a1), "r"(a2), "r"(a3), "r"(b0), "r"(b1));
}

// ---------------------------------------------------------------------------
// tf32 pre-rounding pass
__global__ __launch_bounds__(256) void k_round(const float* __restrict__ src,
                                               float* __restrict__ dst, int n) {
    int i = blockIdx.x * 256 + threadIdx.x;
    if (i < n) dst[i] = rna_tf32(src[i]);
}

// ---------------------------------------------------------------------------
// init: h0/c0 -> hcat/c
__global__ __launch_bounds__(256) void k_init(const float* __restrict__ h0,
                                              const float* __restrict__ c0) {
    int idx = blockIdx.x * 256 + threadIdx.x;   // [2][64][512]
    int d = idx >> 15, b = (idx >> 9) & 63, j = idx & 511;
    g_c[idx] = c0[idx];
    float h = h0[idx];
    g_hcat[b * NH + d * 512 + j] = h;
    g_hcat32[b * NH + d * 512 + j] = rna_tf32(h);
}

// ---------------------------------------------------------------------------
// Unified tf32 MMA core.
// C[col][row] (col = batch-like dim, row = W-row dim), C[col*c_stride + row].
// Warp computes 16 rows x (8*NBM) cols, block = 4 warps = 64-row slab.
// W streamed via cp.async (double buffered); Act staged likewise.
template<int NBM>
__device__ __forceinline__ void mma_core(
    const float* __restrict__ W1, int ldw1,
    const float* __restrict__ W2, int ldw2, int ksplit,
    int K,
    const float* __restrict__ Act, int act_stride, int b0,
    float* __restrict__ C, long long c_stride,
    const float* __restrict__ biasA, const float* __restrict__ biasB,
    int n0, int Nrows)
{
    __shared__ float Wb[2][64][36];
    __shared__ float Ab[2][64][36];
    const int tid = threadIdx.x;
    const int lane = tid & 31, warp = tid >> 5;
    const int g = lane >> 2, c = lane & 3;
    const bool active = (n0 + warp * 16 + 16) <= Nrows;

    float acc[NBM][4];
#pragma unroll
    for (int j = 0; j < NBM; j++)
#pragma unroll
        for (int i = 0; i < 4; i++) acc[j][i] = 0.f;

    const int NC = K >> 5;

    auto stage = [&](int kc, int buf) {
        int k0 = kc << 5;
        const float* Wp; int ld, kk;
        if (k0 < ksplit) { Wp = W1; ld = ldw1; kk = k0; }
        else             { Wp = W2; ld = ldw2; kk = k0 - ksplit; }
#pragma unroll
        for (int i = 0; i < 4; i++) {
            int idx = i * 128 + tid;
            int r = idx >> 3, seg = idx & 7;
            int row = n0 + r; if (row >= Nrows) row = Nrows - 1;
            cp16(&Wb[buf][r][seg * 4], Wp + (size_t)row * ld + kk + seg * 4);
        }
#pragma unroll
        for (int i = 0; i < NBM / 2; i++) {
            int idx = i * 128 + tid;
            int b = idx >> 3, seg = idx & 7;
            cp16(&Ab[buf][b][seg * 4],
                 Act + (size_t)(b0 + b) * act_stride + k0 + seg * 4);
        }
    };

    stage(0, 0);
    cp_commit();

    for (int kc = 0; kc < NC; kc++) {
        int cur = kc & 1;
        if (kc + 1 < NC) stage(kc + 1, cur ^ 1);
        cp_commit();
        cp_wait1();
        __syncthreads();
        if (active) {
            const int r0 = warp * 16 + g, r1 = r0 + 8;
#pragma unroll
            for (int ks = 0; ks < 4; ks++) {
                int kb = ks * 8;
                uint32_t a0 = __float_as_uint(Wb[cur][r0][kb + c]);
                uint32_t a1 = __float_as_uint(Wb[cur][r1][kb + c]);
                uint32_t a2 = __float_as_uint(Wb[cur][r0][kb + c + 4]);
                uint32_t a3 = __float_as_uint(Wb[cur][r1][kb + c + 4]);
#pragma unroll
                for (int j = 0; j < NBM; j++) {
                    uint32_t b0r = __float_as_uint(Ab[cur][g + 8 * j][kb + c]);
                    uint32_t b1r = __float_as_uint(Ab[cur][g + 8 * j][kb + c + 4]);
                    mma_tf32(acc[j], a0, a1, a2, a3, b0r, b1r);
                }
            }
        }
        __syncthreads();
    }

    if (active) {
        int ng0 = n0 + warp * 16 + g, ng1 = ng0 + 8;
        float bv0 = 0.f, bv1 = 0.f;
        if (biasA) { bv0 = biasA[ng0]; bv1 = biasA[ng1]; }
        if (biasB) { bv0 += biasB[ng0]; bv1 += biasB[ng1]; }
#pragma unroll
        for (int j = 0; j < NBM; j++) {
            long long col = b0 + c * 2 + 8 * j;
            C[col * c_stride + ng0]       = acc[j][0] + bv0;
            C[(col + 1) * c_stride + ng0] = acc[j][1] + bv0;
            C[col * c_stride + ng1]       = acc[j][2] + bv1;
            C[(col + 1) * c_stride + ng1] = acc[j][3] + bv1;
        }
    }
}

// ---------------------------------------------------------------------------
// Uk = enc32 @ Ua^T : grid (16 nslab, 1, 256 bslab)
__global__ __launch_bounds__(128) void k_mma_uk() {
    mma_core<8>(g_r_Ua, NH, g_r_Ua, NH, NH, NH,
                g_enc32, NH, blockIdx.z * 64,
                g_Uk, NH, nullptr, nullptr,
                blockIdx.x * 64, NH);
}
// qWa = hcat32 @ Wa^T : grid (16, 4)
__global__ __launch_bounds__(128) void k_mma_qwa() {
    mma_core<2>(g_r_Wa, NH, g_r_Wa, NH, NH, NH,
                g_hcat32, NH, blockIdx.y * 16,
                g_qWa, NH, nullptr, nullptr,
                blockIdx.x * 64, NH);
}
// gates = xcat @ [Wih|Whh]^T + bih + bhh : grid (32, 2, 2)
__global__ __launch_bounds__(128) void k_mma_lstm(const float* __restrict__ bihf,
                                                  const float* __restrict__ bhhf,
                                                  const float* __restrict__ bihb,
                                                  const float* __restrict__ bhhb) {
    int d = blockIdx.z;
    mma_core<4>(g_r_Wih[d], NXK, g_r_Whh[d], ND, NXK, NCK,
                g_xcat + d * NB * NCK, NCK, blockIdx.y * 32,
                g_gates + d * NB * NG, NG,
                d ? bihb : bihf, d ? bhhb : bhhf,
                blockIdx.x * 64, NG);
}
// logits = hcat32 @ outW^T + outb : grid (157, 2)
__global__ __launch_bounds__(128) void k_mma_logits(float* __restrict__ out,
                                                    const float* __restrict__ outb,
                                                    int t) {
    mma_core<4>(g_r_outW, NH, g_r_outW, NH, NH, NH,
                g_hcat32, NH, blockIdx.y * 32,
                out + OUT_LOG + (long long)t * NV, (long long)NT * NV,
                outb, nullptr,
                blockIdx.x * 64, NV);
}

// ---------------------------------------------------------------------------
// scores[b][s] = sum_h Va[h] * tanh(qWa[b][h] + Uk[b][s][h])  (warp per (b,s))
__global__ __launch_bounds__(256) void k_scores(const float* __restrict__ Va) {
    int w = threadIdx.x >> 5, l = threadIdx.x & 31;
    int bs = blockIdx.x * 8 + w;
    int b = bs >> 8;
    const float4* uk = (const float4*)(g_Uk) + bs * (NH / 4);
    const float4* q = (const float4*)(g_qWa) + b * (NH / 4);
    const float4* v = (const float4*)Va;
    float sum = 0.f;
#pragma unroll
    for (int i = 0; i < 8; i++) {
        int idx = l + 32 * i;
        float4 u = uk[idx], qq = q[idx], vv = v[idx];
        sum += vv.x * tanh_fast(u.x + qq.x);
        sum += vv.y * tanh_fast(u.y + qq.y);
        sum += vv.z * tanh_fast(u.z + qq.z);
        sum += vv.w * tanh_fast(u.w + qq.w);
    }
#pragma unroll
    for (int o = 16; o; o >>= 1) sum += __shfl_xor_sync(0xffffffffu, sum, o);
    if (!l) g_scores[bs] = sum;
}

// ---------------------------------------------------------------------------
// softmax over S per b; writes g_w and attentions output
__global__ __launch_bounds__(256) void k_softmax(const unsigned char* __restrict__ mask,
                                                 float* __restrict__ out, int t) {
    int b = blockIdx.x, s = threadIdx.x;
    int lane = s & 31, wid = s >> 5;
    float v = g_scores[b * NS + s];
    if (mask[b * NS + s]) v = -1e30f;
    float m = v;
#pragma unroll
    for (int o = 16; o; o >>= 1) m = fmaxf(m, __shfl_xor_sync(0xffffffffu, m, o));
    __shared__ float red[8];
    if (!lane) red[wid] = m;
    __syncthreads();
    float bm = red[0];
#pragma unroll
    for (int i = 1; i < 8; i++) bm = fmaxf(bm, red[i]);
    float e = __expf(v - bm);
    float sum = e;
#pragma unroll
    for (int o = 16; o; o >>= 1) sum += __shfl_xor_sync(0xffffffffu, sum, o);
    __syncthreads();
    if (!lane) red[wid] = sum;
    __syncthreads();
    float bs = 0.f;
#pragma unroll
    for (int i = 0; i < 8; i++) bs += red[i];
    float w = e / bs;
    g_w[b * NS + s] = w;
    out[b * NT * NS + t * NS + s] = w;
}

// ---------------------------------------------------------------------------
// ctx[b][:] = sum_s w[b][s] * enc[b][s][:]  (fp32, exact enc)
__global__ __launch_bounds__(64) void k_ctx(const float* __restrict__ enc) {
    int b = blockIdx.x >> 2, q = blockIdx.x & 3;
    __shared__ float ws[NS];
    for (int i = threadIdx.x; i < NS; i += 64) ws[i] = g_w[b * NS + i];
    __syncthreads();
    int c = q * 64 + threadIdx.x;
    const float4* e4 = (const float4*)(enc) + (size_t)b * NS * 256 + c;
    float4 acc = make_float4(0.f, 0.f, 0.f, 0.f);
    for (int s = 0; s < NS; s++) {
        float4 ev = e4[(size_t)s * 256];
        float wv = ws[s];
        acc.x += wv * ev.x; acc.y += wv * ev.y;
        acc.z += wv * ev.z; acc.w += wv * ev.w;
    }
    ((float4*)g_ctx)[b * 256 + c] = acc;
}

// ---------------------------------------------------------------------------
// xcat[d][b][:] = rna([emb[tok[b]] | ctx[b] | hcat[d-part]])
__global__ __launch_bounds__(256) void k_xcat(const int* __restrict__ target,
                                              const int* __restrict__ sos,
                                              const float* __restrict__ emb, int t) {
    int idx = blockIdx.x * 256 + threadIdx.x;     // 262144
    int d = idx >> 17;
    int r = idx & 131071;
    int b = r >> 11;
    int j = r & 2047;
    float v;
    if (j < NE) {
        int tok = (t == 0) ? sos[0] : target[b * NT + t - 1];
        v = rna_tf32(emb[tok * NE + j]);
    } else if (j < NXK) {
        v = rna_tf32(g_ctx[b * NH + (j - NE)]);
    } else {
        v = g_hcat32[b * NH + d * 512 + (j - NXK)];
    }
    g_xcat[idx] = v;
}

// ---------------------------------------------------------------------------
// LSTM pointwise; writes c, hcat (exact), hcat32 (rounded)
__global__ __launch_bounds__(256) void k_cell() {
    int idx = blockIdx.x * 256 + threadIdx.x;    // [2][64][512]
    int d = idx >> 15;
    int r = idx & 32767;
    int b = r >> 9;
    int j = r & 511;
    const float* gr = g_gates + d * NB * NG + b * NG;
    float gi = gr[j], gf = gr[512 + j], gg = gr[1024 + j], go = gr[1536 + j];
    float c = g_c[idx];
    float c2 = sigmoid_acc(gf) * c + sigmoid_acc(gi) * tanhf(gg);
    g_c[idx] = c2;
    float h = sigmoid_acc(go) * tanhf(c2);
    g_hcat[b * NH + d * 512 + j] = h;
    g_hcat32[b * NH + d * 512 + j] = rna_tf32(h);
}

// ---------------------------------------------------------------------------
__global__ __launch_bounds__(256) void k_final(float* __restrict__ out) {
    int idx = blockIdx.x * 256 + threadIdx.x;   // [2][64][512]
    int d = idx >> 15, b = (idx >> 9) & 63, j = idx & 511;
    out[OUT_H + idx] = g_hcat[b * NH + d * 512 + j];
    out[OUT_C + idx] = g_c[idx];
}

// ---------------------------------------------------------------------------
extern "C" void kernel_launch(void* const* d_in, const int* in_sizes, int n_in,
                              void* d_out, int out_size) {
    (void)in_sizes; (void)n_in; (void)out_size;
    const float* enc   = (const float*)d_in[0];
    const float* h0    = (const float*)d_in[1];
    const float* c0    = (const float*)d_in[2];
    const int* target  = (const int*)d_in[3];
    const unsigned char* mask = (const unsigned char*)d_in[4];
    const int* sos     = (const int*)d_in[5];
    const float* emb   = (const float*)d_in[6];
    const float* Wa    = (const float*)d_in[7];
    const float* Ua    = (const float*)d_in[8];
    const float* Va    = (const float*)d_in[9];
    const float* outW  = (const float*)d_in[10];
    const float* outb  = (const float*)d_in[11];
    const float* Wihf  = (const float*)d_in[12];
    const float* Whhf  = (const float*)d_in[13];
    const float* bihf  = (const float*)d_in[14];
    const float* bhhf  = (const float*)d_in[15];
    const float* Wihb  = (const float*)d_in[16];
    const float* Whhb  = (const float*)d_in[17];
    const float* bihb  = (const float*)d_in[18];
    const float* bhhb  = (const float*)d_in[19];
    float* out = (float*)d_out;

    float* r_outW; cudaGetSymbolAddress((void**)&r_outW, g_r_outW);
    float* r_Wa;   cudaGetSymbolAddress((void**)&r_Wa,   g_r_Wa);
    float* r_Ua;   cudaGetSymbolAddress((void**)&r_Ua,   g_r_Ua);
    float* r_Wih;  cudaGetSymbolAddress((void**)&r_Wih,  g_r_Wih);
    float* r_Whh;  cudaGetSymbolAddress((void**)&r_Whh,  g_r_Whh);
    float* enc32;  cudaGetSymbolAddress((void**)&enc32,  g_enc32);

    k_init<<<256, 256>>>(h0, c0);
    k_round<<<(NV*NH + 255) / 256, 256>>>(outW, r_outW, NV * NH);
    k_round<<<(NH*NH + 255) / 256, 256>>>(Wa, r_Wa, NH * NH);
    k_round<<<(NH*NH + 255) / 256, 256>>>(Ua, r_Ua, NH * NH);
    k_round<<<(NG*NXK + 255) / 256, 256>>>(Wihf, r_Wih, NG * NXK);
    k_round<<<(NG*NXK + 255) / 256, 256>>>(Wihb, r_Wih + NG * NXK, NG * NXK);
    k_round<<<(NG*ND + 255) / 256, 256>>>(Whhf, r_Whh, NG * ND);
    k_round<<<(NG*ND + 255) / 256, 256>>>(Whhb, r_Whh + NG * ND, NG * ND);
    k_round<<<(NB*NS*NH + 255) / 256, 256>>>(enc, enc32, NB * NS * NH);

    k_mma_uk<<<dim3(16, 1, 256), 128>>>();

    for (int t = 0; t < NT; t++) {
        k_mma_qwa<<<dim3(16, 4), 128>>>();
        k_scores<<<2048, 256>>>(Va);
        k_softmax<<<64, 256>>>(mask, out + OUT_ATTN, t);
        k_ctx<<<256, 64>>>(enc);
        k_xcat<<<1024, 256>>>(target, sos, emb, t);
        k_mma_lstm<<<dim3(32, 2, 2), 128>>>(bihf, bhhf, bihb, bhhb);
        k_cell<<<256, 256>>>();
        k_mma_logits<<<dim3(157, 2), 128>>>(out, outb, t);
    }
    k_final<<<256, 256>>>(out);
}

// round 6
// speedup vs baseline: 2.0205x; 1.2234x over previous
#include <cuda_runtime.h>
#include <math.h>
#include <stdint.h>

// Problem dims
#define NB 64
#define NS 256
#define NH 1024
#define NE 512
#define NV 10000
#define NT 64
#define ND 512
#define NG 2048     // 4*D
#define NCK 2048    // E+H+D
#define NXK 1536    // E+H

// Output layout: decoder_outputs, h, c, attentions
#define OUT_LOG 0
#define OUT_H   (NB*NT*NV)
#define OUT_C   (OUT_H + 2*NB*ND)
#define OUT_ATTN (OUT_C + 2*NB*ND)

// ---------------------------------------------------------------------------
// Scratch (device globals)
__device__ float g_Uk[NB*NS*NH];        // 64 MB
__device__ float g_qWa[NB*NH];
__device__ float g_scores[NB*NS];
__device__ float g_x[NB*NXK];           // [emb | ctx], tf32-rounded
__device__ float g_hcat[NB*NH];         // exact h, [b][dir*512+j]
__device__ float g_hcat32[NB*NH];       // tf32-rounded h
__device__ float g_c[2*NB*ND];
__device__ float g_gates[2*NB*NG];
// tf32-rounded weights / enc
__device__ float g_r_outW[NV*NH];
__device__ float g_r_Wa[NH*NH];
__device__ float g_r_Ua[NH*NH];
__device__ float g_r_Wih[2][NG*NXK];
__device__ float g_r_Whh[2][NG*ND];
__device__ float g_enc32[NB*NS*NH];

// ---------------------------------------------------------------------------
__device__ __forceinline__ float tanh_fast(float x) {
    float y;
    asm("tanh.approx.f32 %0, %1;" : "=f"(y) : "f"(x));
    return y;
}
__device__ __forceinline__ float sigmoid_acc(float x) {
    return 1.0f / (1.0f + __expf(-x));
}
__device__ __forceinline__ float rna_tf32(float x) {
    uint32_t u;
    asm("cvt.rna.tf32.f32 %0, %1;" : "=r"(u) : "f"(x));
    return __uint_as_float(u);
}
__device__ __forceinline__ void cp16(void* s, const void* g) {
    uint32_t sa = (uint32_t)__cvta_generic_to_shared(s);
    asm volatile("cp.async.cg.shared.global [%0], [%1], 16;\n" :: "r"(sa), "l"(g));
}
__device__ __forceinline__ void cp_commit() {
    asm volatile("cp.async.commit_group;\n");
}
__device__ __forceinline__ void cp_wait1() {
    asm volatile("cp.async.wait_group 1;\n");
}
__device__ __forceinline__ void mma_tf32(float (&d)[4], uint32_t a0, uint32_t a1,
                                         uint32_t a2, uint32_t a3,
                                         uint32_t b0, uint32_t b1) {
    asm volatile(
        "mma.sync.aligned.m16n8k8.row.col.f32.tf32.tf32.f32 "
        "{%0,%1,%2,%3}, {%4,%5,%6,%7}, {%8,%9}, {%0,%1,%2,%3};\n"
        : "+f"(d[0]), "+f"(d[1]), "+f"(d[2]), "+f"(d[3])
        : "r"(a0), "r"(a1), "r"(a2), "r"(a3), "r"(b0), "r"(b1));
}

// ---------------------------------------------------------------------------
// Fused tf32 pre-rounding of all weights + enc (single kernel)
#define RN_OUTW (NV*NH)
#define RN_WA   (NH*NH)
#define RN_UA   (NH*NH)
#define RN_WIH  (NG*NXK)
#define RN_WHH  (NG*ND)
#define RN_ENC  (NB*NS*NH)
#define RN_TOT  (RN_OUTW + RN_WA + RN_UA + 2*RN_WIH + 2*RN_WHH + RN_ENC)

__global__ __launch_bounds__(256) void k_round_all(
    const float* __restrict__ outW, const float* __restrict__ Wa,
    const float* __restrict__ Ua,
    const float* __restrict__ Wihf, const float* __restrict__ Wihb,
    const float* __restrict__ Whhf, const float* __restrict__ Whhb,
    const float* __restrict__ enc) {
    long long i = (long long)blockIdx.x * 256 + threadIdx.x;
    if (i >= RN_TOT) return;
    const float* src; float* dst; long long off = i;
    if (off < RN_OUTW) { src = outW; dst = g_r_outW; }
    else if ((off -= RN_OUTW) < RN_WA) { src = Wa; dst = g_r_Wa; }
    else if ((off -= RN_WA) < RN_UA) { src = Ua; dst = g_r_Ua; }
    else if ((off -= RN_UA) < RN_WIH) { src = Wihf; dst = g_r_Wih[0]; }
    else if ((off -= RN_WIH) < RN_WIH) { src = Wihb; dst = g_r_Wih[1]; }
    else if ((off -= RN_WIH) < RN_WHH) { src = Whhf; dst = g_r_Whh[0]; }
    else if ((off -= RN_WHH) < RN_WHH) { src = Whhb; dst = g_r_Whh[1]; }
    else { off -= RN_WHH; src = enc; dst = g_enc32; }
    dst[off] = rna_tf32(src[off]);
}

// ---------------------------------------------------------------------------
__global__ __launch_bounds__(256) void k_init(const float* __restrict__ h0,
                                              const float* __restrict__ c0) {
    int idx = blockIdx.x * 256 + threadIdx.x;   // [2][64][512]
    int d = idx >> 15, b = (idx >> 9) & 63, j = idx & 511;
    g_c[idx] = c0[idx];
    float h = h0[idx];
    g_hcat[b * NH + d * 512 + j] = h;
    g_hcat32[b * NH + d * 512 + j] = rna_tf32(h);
}

// ---------------------------------------------------------------------------
// Unified tf32 MMA core with split W AND split Act at the same K boundary.
template<int NBM>
__device__ __forceinline__ void mma_core(
    const float* __restrict__ W1, int ldw1,
    const float* __restrict__ W2, int ldw2, int ksplit,
    int K,
    const float* __restrict__ Act1, int act1_stride,
    const float* __restrict__ Act2, int act2_stride, int b0,
    float* __restrict__ C, long long c_stride,
    const float* __restrict__ biasA, const float* __restrict__ biasB,
    int n0, int Nrows)
{
    __shared__ float Wb[2][64][36];
    __shared__ float Ab[2][64][36];
    const int tid = threadIdx.x;
    const int lane = tid & 31, warp = tid >> 5;
    const int g = lane >> 2, c = lane & 3;
    const bool active = (n0 + warp * 16 + 16) <= Nrows;

    float acc[NBM][4];
#pragma unroll
    for (int j = 0; j < NBM; j++)
#pragma unroll
        for (int i = 0; i < 4; i++) acc[j][i] = 0.f;

    const int NC = K >> 5;

    auto stage = [&](int kc, int buf) {
        int k0 = kc << 5;
        const float* Wp; const float* Ap; int ldw, lda, kk;
        if (k0 < ksplit) { Wp = W1; ldw = ldw1; Ap = Act1; lda = act1_stride; kk = k0; }
        else { Wp = W2; ldw = ldw2; Ap = Act2; lda = act2_stride; kk = k0 - ksplit; }
#pragma unroll
        for (int i = 0; i < 4; i++) {
            int idx = i * 128 + tid;
            int r = idx >> 3, seg = idx & 7;
            int row = n0 + r; if (row >= Nrows) row = Nrows - 1;
            cp16(&Wb[buf][r][seg * 4], Wp + (size_t)row * ldw + kk + seg * 4);
        }
#pragma unroll
        for (int i = 0; i < NBM / 2; i++) {
            int idx = i * 128 + tid;
            int b = idx >> 3, seg = idx & 7;
            cp16(&Ab[buf][b][seg * 4],
                 Ap + (size_t)(b0 + b) * lda + kk + seg * 4);
        }
    };

    stage(0, 0);
    cp_commit();

    for (int kc = 0; kc < NC; kc++) {
        int cur = kc & 1;
        if (kc + 1 < NC) stage(kc + 1, cur ^ 1);
        cp_commit();
        cp_wait1();
        __syncthreads();
        if (active) {
            const int r0 = warp * 16 + g, r1 = r0 + 8;
#pragma unroll
            for (int ks = 0; ks < 4; ks++) {
                int kb = ks * 8;
                uint32_t a0 = __float_as_uint(Wb[cur][r0][kb + c]);
                uint32_t a1 = __float_as_uint(Wb[cur][r1][kb + c]);
                uint32_t a2 = __float_as_uint(Wb[cur][r0][kb + c + 4]);
                uint32_t a3 = __float_as_uint(Wb[cur][r1][kb + c + 4]);
#pragma unroll
                for (int j = 0; j < NBM; j++) {
                    uint32_t b0r = __float_as_uint(Ab[cur][g + 8 * j][kb + c]);
                    uint32_t b1r = __float_as_uint(Ab[cur][g + 8 * j][kb + c + 4]);
                    mma_tf32(acc[j], a0, a1, a2, a3, b0r, b1r);
                }
            }
        }
        __syncthreads();
    }

    if (active) {
        int ng0 = n0 + warp * 16 + g, ng1 = ng0 + 8;
        float bv0 = 0.f, bv1 = 0.f;
        if (biasA) { bv0 = biasA[ng0]; bv1 = biasA[ng1]; }
        if (biasB) { bv0 += biasB[ng0]; bv1 += biasB[ng1]; }
#pragma unroll
        for (int j = 0; j < NBM; j++) {
            long long col = b0 + c * 2 + 8 * j;
            C[col * c_stride + ng0]       = acc[j][0] + bv0;
            C[(col + 1) * c_stride + ng0] = acc[j][1] + bv0;
            C[col * c_stride + ng1]       = acc[j][2] + bv1;
            C[(col + 1) * c_stride + ng1] = acc[j][3] + bv1;
        }
    }
}

// ---------------------------------------------------------------------------
// Uk = enc32 @ Ua^T : grid (16, 1, 256)
__global__ __launch_bounds__(128) void k_mma_uk() {
    mma_core<8>(g_r_Ua, NH, g_r_Ua, NH, NH, NH,
                g_enc32, NH, g_enc32, NH, blockIdx.z * 64,
                g_Uk, NH, nullptr, nullptr,
                blockIdx.x * 64, NH);
}
// qWa = hcat32 @ Wa^T : grid (16, 4)
__global__ __launch_bounds__(128) void k_mma_qwa() {
    mma_core<2>(g_r_Wa, NH, g_r_Wa, NH, NH, NH,
                g_hcat32, NH, g_hcat32, NH, blockIdx.y * 16,
                g_qWa, NH, nullptr, nullptr,
                blockIdx.x * 64, NH);
}
// gates = [x | h_d] @ [Wih_d | Whh_d]^T + biases : grid (32, 2, 2)
__global__ __launch_bounds__(128) void k_mma_lstm(const float* __restrict__ bihf,
                                                  const float* __restrict__ bhhf,
                                                  const float* __restrict__ bihb,
                                                  const float* __restrict__ bhhb) {
    int d = blockIdx.z;
    mma_core<4>(g_r_Wih[d], NXK, g_r_Whh[d], ND, NXK, NCK,
                g_x, NXK, g_hcat32 + d * 512, NH, blockIdx.y * 32,
                g_gates + d * NB * NG, NG,
                d ? bihb : bihf, d ? bhhb : bhhf,
                blockIdx.x * 64, NG);
}
// logits = hcat32 @ outW^T + outb : grid (157, 2)
__global__ __launch_bounds__(128) void k_mma_logits(float* __restrict__ out,
                                                    const float* __restrict__ outb,
                                                    int t) {
    mma_core<4>(g_r_outW, NH, g_r_outW, NH, NH, NH,
                g_hcat32, NH, g_hcat32, NH, blockIdx.y * 32,
                out + OUT_LOG + (long long)t * NV, (long long)NT * NV,
                outb, nullptr,
                blockIdx.x * 64, NV);
}

// ---------------------------------------------------------------------------
// scores[b][s] = sum_h Va[h] * tanh(qWa[b][h] + Uk[b][s][h])  (warp per (b,s))
__global__ __launch_bounds__(256) void k_scores(const float* __restrict__ Va) {
    int w = threadIdx.x >> 5, l = threadIdx.x & 31;
    int bs = blockIdx.x * 8 + w;
    int b = bs >> 8;
    const float4* uk = (const float4*)(g_Uk) + bs * (NH / 4);
    const float4* q = (const float4*)(g_qWa) + b * (NH / 4);
    const float4* v = (const float4*)Va;
    float sum = 0.f;
#pragma unroll
    for (int i = 0; i < 8; i++) {
        int idx = l + 32 * i;
        float4 u = uk[idx], qq = q[idx], vv = v[idx];
        sum += vv.x * tanh_fast(u.x + qq.x);
        sum += vv.y * tanh_fast(u.y + qq.y);
        sum += vv.z * tanh_fast(u.z + qq.z);
        sum += vv.w * tanh_fast(u.w + qq.w);
    }
#pragma unroll
    for (int o = 16; o; o >>= 1) sum += __shfl_xor_sync(0xffffffffu, sum, o);
    if (!l) g_scores[bs] = sum;
}

// ---------------------------------------------------------------------------
// Fused softmax + ctx + x-build + attn-out.
// grid (4 quarters, 64 b), 256 threads.
__global__ __launch_bounds__(256) void k_smctx(const unsigned char* __restrict__ mask,
                                               const float* __restrict__ enc,
                                               const float* __restrict__ emb,
                                               const int* __restrict__ target,
                                               const int* __restrict__ sos,
                                               float* __restrict__ out, int t) {
    int q = blockIdx.x, b = blockIdx.y;
    int tid = threadIdx.x;
    int lane = tid & 31, wid = tid >> 5;
    __shared__ float red[8];
    __shared__ float ws[NS];
    __shared__ float4 part[4][64];

    // --- softmax ---
    float v = g_scores[b * NS + tid];
    if (mask[b * NS + tid]) v = -1e30f;
    float m = v;
#pragma unroll
    for (int o = 16; o; o >>= 1) m = fmaxf(m, __shfl_xor_sync(0xffffffffu, m, o));
    if (!lane) red[wid] = m;
    __syncthreads();
    float bm = red[0];
#pragma unroll
    for (int i = 1; i < 8; i++) bm = fmaxf(bm, red[i]);
    float e = __expf(v - bm);
    float sum = e;
#pragma unroll
    for (int o = 16; o; o >>= 1) sum += __shfl_xor_sync(0xffffffffu, sum, o);
    __syncthreads();
    if (!lane) red[wid] = sum;
    __syncthreads();
    float bsum = 0.f;
#pragma unroll
    for (int i = 0; i < 8; i++) bsum += red[i];
    float w = e / bsum;
    ws[tid] = w;
    if (q == 0) out[OUT_ATTN + b * NT * NS + t * NS + tid] = w;

    // --- emb part of x : 128 floats per quarter ---
    if (tid < 128) {
        int tok = (t == 0) ? sos[0] : target[b * NT + t - 1];
        int j = q * 128 + tid;
        g_x[b * NXK + j] = rna_tf32(emb[tok * NE + j]);
    }
    __syncthreads();

    // --- ctx quarter: 64 float4 cols x 4 s-groups ---
    int c4 = q * 64 + (tid & 63);              // float4 col in H (0..255)
    int sg = tid >> 6;                         // 0..3
    const float4* e4 = (const float4*)(enc) + (size_t)b * NS * 256 + c4;
    float4 acc = make_float4(0.f, 0.f, 0.f, 0.f);
#pragma unroll 4
    for (int s = sg * 64; s < sg * 64 + 64; s++) {
        float4 ev = e4[(size_t)s * 256];
        float wv = ws[s];
        acc.x += wv * ev.x; acc.y += wv * ev.y;
        acc.z += wv * ev.z; acc.w += wv * ev.w;
    }
    part[sg][tid & 63] = acc;
    __syncthreads();
    if (tid < 64) {
        float4 a0 = part[0][tid], a1 = part[1][tid],
               a2 = part[2][tid], a3 = part[3][tid];
        float4 r = make_float4(a0.x + a1.x + a2.x + a3.x,
                               a0.y + a1.y + a2.y + a3.y,
                               a0.z + a1.z + a2.z + a3.z,
                               a0.w + a1.w + a2.w + a3.w);
        float* xp = g_x + b * NXK + NE + q * 256 + tid * 4;
        xp[0] = rna_tf32(r.x); xp[1] = rna_tf32(r.y);
        xp[2] = rna_tf32(r.z); xp[3] = rna_tf32(r.w);
    }
}

// ---------------------------------------------------------------------------
// LSTM pointwise; writes c, hcat (exact), hcat32 (rounded)
__global__ __launch_bounds__(256) void k_cell() {
    int idx = blockIdx.x * 256 + threadIdx.x;    // [2][64][512]
    int d = idx >> 15;
    int r = idx & 32767;
    int b = r >> 9;
    int j = r & 511;
    const float* gr = g_gates + d * NB * NG + b * NG;
    float gi = gr[j], gf = gr[512 + j], gg = gr[1024 + j], go = gr[1536 + j];
    float c = g_c[idx];
    float c2 = sigmoid_acc(gf) * c + sigmoid_acc(gi) * tanhf(gg);
    g_c[idx] = c2;
    float h = sigmoid_acc(go) * tanhf(c2);
    g_hcat[b * NH + d * 512 + j] = h;
    g_hcat32[b * NH + d * 512 + j] = rna_tf32(h);
}

// ---------------------------------------------------------------------------
__global__ __launch_bounds__(256) void k_final(float* __restrict__ out) {
    int idx = blockIdx.x * 256 + threadIdx.x;   // [2][64][512]
    int d = idx >> 15, b = (idx >> 9) & 63, j = idx & 511;
    out[OUT_H + idx] = g_hcat[b * NH + d * 512 + j];
    out[OUT_C + idx] = g_c[idx];
}

// ---------------------------------------------------------------------------
extern "C" void kernel_launch(void* const* d_in, const int* in_sizes, int n_in,
                              void* d_out, int out_size) {
    (void)in_sizes; (void)n_in; (void)out_size;
    const float* enc   = (const float*)d_in[0];
    const float* h0    = (const float*)d_in[1];
    const float* c0    = (const float*)d_in[2];
    const int* target  = (const int*)d_in[3];
    const unsigned char* mask = (const unsigned char*)d_in[4];
    const int* sos     = (const int*)d_in[5];
    const float* emb   = (const float*)d_in[6];
    const float* Wa    = (const float*)d_in[7];
    const float* Ua    = (const float*)d_in[8];
    const float* Va    = (const float*)d_in[9];
    const float* outW  = (const float*)d_in[10];
    const float* outb  = (const float*)d_in[11];
    const float* Wihf  = (const float*)d_in[12];
    const float* Whhf  = (const float*)d_in[13];
    const float* bihf  = (const float*)d_in[14];
    const float* bhhf  = (const float*)d_in[15];
    const float* Wihb  = (const float*)d_in[16];
    const float* Whhb  = (const float*)d_in[17];
    const float* bihb  = (const float*)d_in[18];
    const float* bhhb  = (const float*)d_in[19];
    float* out = (float*)d_out;

    k_init<<<256, 256>>>(h0, c0);
    k_round_all<<<(int)((RN_TOT + 255) / 256), 256>>>(outW, Wa, Ua, Wihf, Wihb,
                                                      Whhf, Whhb, enc);
    k_mma_uk<<<dim3(16, 1, 256), 128>>>();

    for (int t = 0; t < NT; t++) {
        k_mma_qwa<<<dim3(16, 4), 128>>>();
        k_scores<<<2048, 256>>>(Va);
        k_smctx<<<dim3(4, 64), 256>>>(mask, enc, emb, target, sos, out, t);
        k_mma_lstm<<<dim3(32, 2, 2), 128>>>(bihf, bhhf, bihb, bhhb);
        k_cell<<<256, 256>>>();
        k_mma_logits<<<dim3(157, 2), 128>>>(out, outb, t);
    }
    k_final<<<256, 256>>>(out);
}

// round 9
// speedup vs baseline: 2.7395x; 1.3559x over previous
#include <cuda_runtime.h>
#include <math.h>
#include <stdint.h>

// Problem dims
#define NB 64
#define NS 256
#define NH 1024
#define NE 512
#define NV 10000
#define NT 64
#define ND 512
#define NG 2048     // 4*D
#define NXK 1536    // E+H

// Output layout: decoder_outputs, h, c, attentions
#define OUT_LOG 0
#define OUT_H   (NB*NT*NV)
#define OUT_C   (OUT_H + 2*NB*ND)
#define OUT_ATTN (OUT_C + 2*NB*ND)

// ---------------------------------------------------------------------------
// Scratch (device globals)
__device__ float g_Uk[NB*NS*NH];          // 64 MB
__device__ float g_qWa_part[4][NB*NH];    // split-K qWa partials
__device__ float g_scores[NB*NS];
__device__ float g_x[NB*NXK];             // [emb | ctx], tf32-rounded
__device__ float g_hcat[NB*NH];           // exact h, [b][dir*512+j]
__device__ float g_hcat32[NB*NH];         // tf32-rounded h
__device__ float g_c[2*NB*ND];
__device__ float g_gates_part[4][2][NB*NG]; // split-K gate partials
// tf32-rounded weights / enc
__device__ float g_r_outW[NV*NH];
__device__ float g_r_Wa[NH*NH];
__device__ float g_r_Ua[NH*NH];
__device__ float g_r_Wih[2][NG*NXK];
__device__ float g_r_Whh[2][NG*ND];
__device__ float g_enc32[NB*NS*NH];

// ---------------------------------------------------------------------------
__device__ __forceinline__ float tanh_fast(float x) {
    float y;
    asm("tanh.approx.f32 %0, %1;" : "=f"(y) : "f"(x));
    return y;
}
__device__ __forceinline__ float sigmoid_acc(float x) {
    return 1.0f / (1.0f + __expf(-x));
}
__device__ __forceinline__ float rna_tf32(float x) {
    uint32_t u;
    asm("cvt.rna.tf32.f32 %0, %1;" : "=r"(u) : "f"(x));
    return __uint_as_float(u);
}
__device__ __forceinline__ void cp16(void* s, const void* g) {
    uint32_t sa = (uint32_t)__cvta_generic_to_shared(s);
    asm volatile("cp.async.cg.shared.global [%0], [%1], 16;\n" :: "r"(sa), "l"(g));
}
__device__ __forceinline__ void cp_commit() {
    asm volatile("cp.async.commit_group;\n");
}
__device__ __forceinline__ void cp_wait1() {
    asm volatile("cp.async.wait_group 1;\n");
}
__device__ __forceinline__ void mma_tf32(float (&d)[4], uint32_t a0, uint32_t a1,
                                         uint32_t a2, uint32_t a3,
                                         uint32_t b0, uint32_t b1) {
    asm volatile(
        "mma.sync.aligned.m16n8k8.row.col.f32.tf32.tf32.f32 "
        "{%0,%1,%2,%3}, {%4,%5,%6,%7}, {%8,%9}, {%0,%1,%2,%3};\n"
        : "+f"(d[0]), "+f"(d[1]), "+f"(d[2]), "+f"(d[3])
        : "r"(a0), "r"(a1), "r"(a2), "r"(a3), "r"(b0), "r"(b1));
}

// ---------------------------------------------------------------------------
// Fused tf32 pre-rounding of all weights + enc
#define RN_OUTW (NV*NH)
#define RN_WA   (NH*NH)
#define RN_UA   (NH*NH)
#define RN_WIH  (NG*NXK)
#define RN_WHH  (NG*ND)
#define RN_ENC  (NB*NS*NH)
#define RN_TOT  (RN_OUTW + RN_WA + RN_UA + 2*RN_WIH + 2*RN_WHH + RN_ENC)

__global__ __launch_bounds__(256) void k_round_all(
    const float* __restrict__ outW, const float* __restrict__ Wa,
    const float* __restrict__ Ua,
    const float* __restrict__ Wihf, const float* __restrict__ Wihb,
    const float* __restrict__ Whhf, const float* __restrict__ Whhb,
    const float* __restrict__ enc) {
    long long i = (long long)blockIdx.x * 256 + threadIdx.x;
    if (i >= RN_TOT) return;
    const float* src; float* dst; long long off = i;
    if (off < RN_OUTW) { src = outW; dst = g_r_outW; }
    else if ((off -= RN_OUTW) < RN_WA) { src = Wa; dst = g_r_Wa; }
    else if ((off -= RN_WA) < RN_UA) { src = Ua; dst = g_r_Ua; }
    else if ((off -= RN_UA) < RN_WIH) { src = Wihf; dst = g_r_Wih[0]; }
    else if ((off -= RN_WIH) < RN_WIH) { src = Wihb; dst = g_r_Wih[1]; }
    else if ((off -= RN_WIH) < RN_WHH) { src = Whhf; dst = g_r_Whh[0]; }
    else if ((off -= RN_WHH) < RN_WHH) { src = Whhb; dst = g_r_Whh[1]; }
    else { off -= RN_WHH; src = enc; dst = g_enc32; }
    dst[off] = rna_tf32(src[off]);
}

// ---------------------------------------------------------------------------
__global__ __launch_bounds__(256) void k_init(const float* __restrict__ h0,
                                              const float* __restrict__ c0) {
    int idx = blockIdx.x * 256 + threadIdx.x;   // [2][64][512]
    int d = idx >> 15, b = (idx >> 9) & 63, j = idx & 511;
    g_c[idx] = c0[idx];
    float h = h0[idx];
    g_hcat[b * NH + d * 512 + j] = h;
    g_hcat32[b * NH + d * 512 + j] = rna_tf32(h);
}

// ---------------------------------------------------------------------------
// tf32 MMA core: 64 W-rows x 64 act-cols per block (4 warps x 16 rows, NBM=8),
// single W / Act source, K-chunk 32 double-buffered via cp.async.
__device__ __forceinline__ void mma8_core(
    const float* __restrict__ W, int ldw,
    const float* __restrict__ Act, int lda, int b0,
    int K,
    float* __restrict__ C, long long c_stride,
    const float* __restrict__ bias,
    int n0, int Nrows)
{
    __shared__ float Wb[2][64][36];
    __shared__ float Ab[2][64][36];
    const int tid = threadIdx.x;
    const int lane = tid & 31, warp = tid >> 5;
    const int g = lane >> 2, c = lane & 3;
    const bool active = (n0 + warp * 16 + 16) <= Nrows;

    float acc[8][4];
#pragma unroll
    for (int j = 0; j < 8; j++)
#pragma unroll
        for (int i = 0; i < 4; i++) acc[j][i] = 0.f;

    const int NC = K >> 5;

    auto stage = [&](int kc, int buf) {
        int k0 = kc << 5;
#pragma unroll
        for (int i = 0; i < 4; i++) {
            int idx = i * 128 + tid;
            int r = idx >> 3, seg = idx & 7;
            int row = n0 + r; if (row >= Nrows) row = Nrows - 1;
            cp16(&Wb[buf][r][seg * 4], W + (size_t)row * ldw + k0 + seg * 4);
        }
#pragma unroll
        for (int i = 0; i < 4; i++) {
            int idx = i * 128 + tid;
            int b = idx >> 3, seg = idx & 7;
            cp16(&Ab[buf][b][seg * 4],
                 Act + (size_t)(b0 + b) * lda + k0 + seg * 4);
        }
    };

    stage(0, 0);
    cp_commit();

    for (int kc = 0; kc < NC; kc++) {
        int cur = kc & 1;
        if (kc + 1 < NC) stage(kc + 1, cur ^ 1);
        cp_commit();
        cp_wait1();
        __syncthreads();
        if (active) {
            const int r0 = warp * 16 + g, r1 = r0 + 8;
#pragma unroll
            for (int ks = 0; ks < 4; ks++) {
                int kb = ks * 8;
                uint32_t a0 = __float_as_uint(Wb[cur][r0][kb + c]);
                uint32_t a1 = __float_as_uint(Wb[cur][r1][kb + c]);
                uint32_t a2 = __float_as_uint(Wb[cur][r0][kb + c + 4]);
                uint32_t a3 = __float_as_uint(Wb[cur][r1][kb + c + 4]);
#pragma unroll
                for (int j = 0; j < 8; j++) {
                    uint32_t b0r = __float_as_uint(Ab[cur][g + 8 * j][kb + c]);
                    uint32_t b1r = __float_as_uint(Ab[cur][g + 8 * j][kb + c + 4]);
                    mma_tf32(acc[j], a0, a1, a2, a3, b0r, b1r);
                }
            }
        }
        __syncthreads();
    }

    if (active) {
        int ng0 = n0 + warp * 16 + g, ng1 = ng0 + 8;
        float bv0 = 0.f, bv1 = 0.f;
        if (bias) { bv0 = bias[ng0]; bv1 = bias[ng1]; }
#pragma unroll
        for (int j = 0; j < 8; j++) {
            long long col = b0 + c * 2 + 8 * j;
            C[col * c_stride + ng0]       = acc[j][0] + bv0;
            C[(col + 1) * c_stride + ng0] = acc[j][1] + bv0;
            C[col * c_stride + ng1]       = acc[j][2] + bv1;
            C[(col + 1) * c_stride + ng1] = acc[j][3] + bv1;
        }
    }
}

// ---------------------------------------------------------------------------
// qwa split-K block helper: qid in [0,64)
__device__ __forceinline__ void qwa_block(int qid) {
    int n0 = (qid & 15) * 64;
    int ks = qid >> 4;                       // 0..3, K-chunk 256
    mma8_core(g_r_Wa + ks * 256, NH,
              g_hcat32 + ks * 256, NH, 0,
              256,
              g_qWa_part[ks], NH, nullptr,
              n0, NH);
}

// Uk = enc32 @ Ua^T : grid (16, 1, 256)
__global__ __launch_bounds__(128) void k_mma_uk() {
    mma8_core(g_r_Ua, NH, g_enc32, NH, blockIdx.z * 64,
              NH, g_Uk, NH, nullptr, blockIdx.x * 64, NH);
}

// qWa partials only (prologue, t=0)
__global__ __launch_bounds__(128) void k_qwa0() {
    qwa_block(blockIdx.x);
}

// Combo: logits(t) [bids 0..156] + qWa partials for t+1 [bids 157..220]
__global__ __launch_bounds__(128) void k_combo(float* __restrict__ out,
                                               const float* __restrict__ outb,
                                               int t) {
    int bid = blockIdx.x;
    if (bid < 157) {
        mma8_core(g_r_outW, NH, g_hcat32, NH, 0,
                  NH,
                  out + OUT_LOG + (long long)t * NV, (long long)NT * NV,
                  outb, bid * 64, NV);
    } else {
        qwa_block(bid - 157);
    }
}

// LSTM gates split-K: grid 256 = 32 n-slabs x 4 ks x 2 dir
__global__ __launch_bounds__(128) void k_mma_lstm() {
    int bid = blockIdx.x;
    int n0 = (bid & 31) * 64;
    int ks = (bid >> 5) & 3;
    int d = bid >> 7;
    const float* W; const float* Act; int ldw, lda;
    if (ks < 3) { W = g_r_Wih[d] + ks * 512; ldw = NXK;
                  Act = g_x + ks * 512;      lda = NXK; }
    else        { W = g_r_Whh[d];            ldw = ND;
                  Act = g_hcat32 + d * 512;  lda = NH; }
    mma8_core(W, ldw, Act, lda, 0, 512,
              g_gates_part[ks][d], NG, nullptr, n0, NG);
}

// ---------------------------------------------------------------------------
// scores: block = (b, 8 s-values); stages qWa partial-sum in smem once.
__global__ __launch_bounds__(256) void k_scores(const float* __restrict__ Va) {
    int b = blockIdx.x >> 5;
    int s0 = (blockIdx.x & 31) * 8;
    int tid = threadIdx.x;
    __shared__ float4 qs[256];               // qWa[b][:] summed over 4 partials
    {
        float4 p0 = ((const float4*)g_qWa_part[0])[b * 256 + tid];
        float4 p1 = ((const float4*)g_qWa_part[1])[b * 256 + tid];
        float4 p2 = ((const float4*)g_qWa_part[2])[b * 256 + tid];
        float4 p3 = ((const float4*)g_qWa_part[3])[b * 256 + tid];
        qs[tid] = make_float4(p0.x + p1.x + p2.x + p3.x,
                              p0.y + p1.y + p2.y + p3.y,
                              p0.z + p1.z + p2.z + p3.z,
                              p0.w + p1.w + p2.w + p3.w);
    }
    __syncthreads();
    int w = tid >> 5, l = tid & 31;
    int bs = b * NS + s0 + w;
    const float4* uk = (const float4*)(g_Uk) + (size_t)bs * (NH / 4);
    const float4* v = (const float4*)Va;
    float sum = 0.f;
#pragma unroll
    for (int i = 0; i < 8; i++) {
        int idx = l + 32 * i;
        float4 u = uk[idx], qq = qs[idx], vv = v[idx];
        sum += vv.x * tanh_fast(u.x + qq.x);
        sum += vv.y * tanh_fast(u.y + qq.y);
        sum += vv.z * tanh_fast(u.z + qq.z);
        sum += vv.w * tanh_fast(u.w + qq.w);
    }
#pragma unroll
    for (int o = 16; o; o >>= 1) sum += __shfl_xor_sync(0xffffffffu, sum, o);
    if (!l) g_scores[bs] = sum;
}

// ---------------------------------------------------------------------------
// Fused softmax + ctx + x-build + attn-out. grid (4 quarters, 64 b), 256 thr.
__global__ __launch_bounds__(256) void k_smctx(const unsigned char* __restrict__ mask,
                                               const float* __restrict__ enc,
                                               const float* __restrict__ emb,
                                               const int* __restrict__ target,
                                               const int* __restrict__ sos,
                                               float* __restrict__ out, int t) {
    int q = blockIdx.x, b = blockIdx.y;
    int tid = threadIdx.x;
    int lane = tid & 31, wid = tid >> 5;
    __shared__ float red[8];
    __shared__ float ws[NS];
    __shared__ float4 part[4][64];

    // --- softmax ---
    float v = g_scores[b * NS + tid];
    if (mask[b * NS + tid]) v = -1e30f;
    float m = v;
#pragma unroll
    for (int o = 16; o; o >>= 1) m = fmaxf(m, __shfl_xor_sync(0xffffffffu, m, o));
    if (!lane) red[wid] = m;
    __syncthreads();
    float bm = red[0];
#pragma unroll
    for (int i = 1; i < 8; i++) bm = fmaxf(bm, red[i]);
    float e = __expf(v - bm);
    float sum = e;
#pragma unroll
    for (int o = 16; o; o >>= 1) sum += __shfl_xor_sync(0xffffffffu, sum, o);
    __syncthreads();
    if (!lane) red[wid] = sum;
    __syncthreads();
    float bsum = 0.f;
#pragma unroll
    for (int i = 0; i < 8; i++) bsum += red[i];
    float w = e / bsum;
    ws[tid] = w;
    if (q == 0) out[OUT_ATTN + b * NT * NS + t * NS + tid] = w;

    // --- emb part of x : 128 floats per quarter ---
    if (tid < 128) {
        int tok = (t == 0) ? sos[0] : target[b * NT + t - 1];
        int j = q * 128 + tid;
        g_x[b * NXK + j] = rna_tf32(emb[tok * NE + j]);
    }
    __syncthreads();

    // --- ctx quarter: 64 float4 cols x 4 s-groups ---
    int c4 = q * 64 + (tid & 63);
    int sg = tid >> 6;
    const float4* e4 = (const float4*)(enc) + (size_t)b * NS * 256 + c4;
    float4 acc = make_float4(0.f, 0.f, 0.f, 0.f);
#pragma unroll 4
    for (int s = sg * 64; s < sg * 64 + 64; s++) {
        float4 ev = e4[(size_t)s * 256];
        float wv = ws[s];
        acc.x += wv * ev.x; acc.y += wv * ev.y;
        acc.z += wv * ev.z; acc.w += wv * ev.w;
    }
    part[sg][tid & 63] = acc;
    __syncthreads();
    if (tid < 64) {
        float4 a0 = part[0][tid], a1 = part[1][tid],
               a2 = part[2][tid], a3 = part[3][tid];
        float4 r = make_float4(a0.x + a1.x + a2.x + a3.x,
                               a0.y + a1.y + a2.y + a3.y,
                               a0.z + a1.z + a2.z + a3.z,
                               a0.w + a1.w + a2.w + a3.w);
        float* xp = g_x + b * NXK + NE + q * 256 + tid * 4;
        xp[0] = rna_tf32(r.x); xp[1] = rna_tf32(r.y);
        xp[2] = rna_tf32(r.z); xp[3] = rna_tf32(r.w);
    }
}

// ---------------------------------------------------------------------------
// LSTM pointwise: sums 4 gate partials + biases, writes c/hcat/hcat32.
__global__ __launch_bounds__(256) void k_cell(const float* __restrict__ bihf,
                                              const float* __restrict__ bhhf,
                                              const float* __restrict__ bihb,
                                              const float* __restrict__ bhhb) {
    int idx = blockIdx.x * 256 + threadIdx.x;    // [2][64][512]
    int d = idx >> 15;
    int r = idx & 32767;
    int b = r >> 9;
    int j = r & 511;
    const float* bih = d ? bihb : bihf;
    const float* bhh = d ? bhhb : bhhf;
    float gv[4];
#pragma unroll
    for (int g4 = 0; g4 < 4; g4++) {
        int gi = g4 * 512 + j;
        float s = bih[gi] + bhh[gi];
#pragma unroll
        for (int ks = 0; ks < 4; ks++)
            s += g_gates_part[ks][d][b * NG + gi];
        gv[g4] = s;
    }
    float c = g_c[idx];
    float c2 = sigmoid_acc(gv[1]) * c + sigmoid_acc(gv[0]) * tanhf(gv[2]);
    g_c[idx] = c2;
    float h = sigmoid_acc(gv[3]) * tanhf(c2);
    g_hcat[b * NH + d * 512 + j] = h;
    g_hcat32[b * NH + d * 512 + j] = rna_tf32(h);
}

// ---------------------------------------------------------------------------
__global__ __launch_bounds__(256) void k_final(float* __restrict__ out) {
    int idx = blockIdx.x * 256 + threadIdx.x;   // [2][64][512]
    int d = idx >> 15, b = (idx >> 9) & 63, j = idx & 511;
    out[OUT_H + idx] = g_hcat[b * NH + d * 512 + j];
    out[OUT_C + idx] = g_c[idx];
}

// ---------------------------------------------------------------------------
extern "C" void kernel_launch(void* const* d_in, const int* in_sizes, int n_in,
                              void* d_out, int out_size) {
    (void)in_sizes; (void)n_in; (void)out_size;
    const float* enc   = (const float*)d_in[0];
    const float* h0    = (const float*)d_in[1];
    const float* c0    = (const float*)d_in[2];
    const int* target  = (const int*)d_in[3];
    const unsigned char* mask = (const unsigned char*)d_in[4];
    const int* sos     = (const int*)d_in[5];
    const float* emb   = (const float*)d_in[6];
    const float* Wa    = (const float*)d_in[7];
    const float* Ua    = (const float*)d_in[8];
    const float* Va    = (const float*)d_in[9];
    const float* outW  = (const float*)d_in[10];
    const float* outb  = (const float*)d_in[11];
    const float* Wihf  = (const float*)d_in[12];
    const float* Whhf  = (const float*)d_in[13];
    const float* bihf  = (const float*)d_in[14];
    const float* bhhf  = (const float*)d_in[15];
    const float* Wihb  = (const float*)d_in[16];
    const float* Whhb  = (const float*)d_in[17];
    const float* bihb  = (const float*)d_in[18];
    const float* bhhb  = (const float*)d_in[19];
    float* out = (float*)d_out;

    k_init<<<256, 256>>>(h0, c0);
    k_round_all<<<(int)((RN_TOT + 255) / 256), 256>>>(outW, Wa, Ua, Wihf, Wihb,
                                                      Whhf, Whhb, enc);
    k_mma_uk<<<dim3(16, 1, 256), 128>>>();
    k_qwa0<<<64, 128>>>();

    for (int t = 0; t < NT; t++) {
        k_scores<<<2048, 256>>>(Va);
        k_smctx<<<dim3(4, 64), 256>>>(mask, enc, emb, target, sos, out, t);
        k_mma_lstm<<<256, 128>>>();
        k_cell<<<256, 256>>>(bihf, bhhf, bihb, bhhb);
        k_combo<<<221, 128>>>(out, outb, t);
    }
    k_final<<<256, 256>>>(out);
}